// round 4
// baseline (speedup 1.0000x reference)
#include <cuda_runtime.h>
#include <cuda_fp16.h>
#include <cstdint>

// out[b,o] = sum_i tanh(x[b,i]*t) * W[o,i],  W = sum_p coef[o,i,p]
// B=131072, I=O=128. fp32 in/out.
//
// mma.sync.m16n8k16 fp16 (fp32 accum), fp16 W (rel_err ~2.7e-4).
// Multi-tile CTAs (4 x 64 rows), reg-prefetch pipeline, B copied once/CTA.

static constexpr int IDIM = 128;
static constexpr int ODIM = 128;
static constexpr int TILE_M = 64;
static constexpr int TILES = 4;

// B fragments in mma register layout: [nt(16)][kt(8)][lane(32)][reg(2)]
__device__ uint32_t g_BF[16 * 8 * 32 * 2];   // 32KB, L2-hot

// ---------------------------------------------------------------------------
__global__ void prep_w_kernel(const float* __restrict__ coef) {
    int idx = blockIdx.x * blockDim.x + threadIdx.x;   // 0..8191
    int nt = idx >> 9;
    int kt = (idx >> 6) & 7;
    int lane = (idx >> 1) & 31;
    int reg = idx & 1;
    int n = nt * 8 + (lane >> 2);
    int k = kt * 16 + (lane & 3) * 2 + reg * 8;

    const float4* c0 = reinterpret_cast<const float4*>(coef + ((size_t)n * 128 + k) * 16);
    const float4* c1 = reinterpret_cast<const float4*>(coef + ((size_t)n * 128 + k + 1) * 16);
    float4 v[8];
#pragma unroll
    for (int j = 0; j < 4; j++) v[j] = c0[j];        // MLP: all loads in flight
#pragma unroll
    for (int j = 0; j < 4; j++) v[4 + j] = c1[j];
    float s0 = 0.f, s1 = 0.f;
#pragma unroll
    for (int j = 0; j < 4; j++) s0 += (v[j].x + v[j].y) + (v[j].z + v[j].w);
#pragma unroll
    for (int j = 0; j < 4; j++) s1 += (v[4 + j].x + v[4 + j].y) + (v[4 + j].z + v[4 + j].w);
    __half2 hh = __floats2half2_rn(s0, s1);
    g_BF[((nt * 8 + kt) * 32 + lane) * 2 + reg] = *reinterpret_cast<uint32_t*>(&hh);
}

// ---------------------------------------------------------------------------
__device__ __forceinline__ float tanh_acc(float v) {
    v = fminf(fmaxf(v, -10.f), 10.f);
    float e = __expf(2.f * v);
    return __fdividef(e - 1.f, e + 1.f);
}

__device__ __forceinline__ uint32_t pack_h2(float a, float b) {
    __half2 h = __floats2half2_rn(a, b);
    return *reinterpret_cast<uint32_t*>(&h);
}

#define MMA16816(d0, d1, d2, d3, A, b0, b1)                                   \
    asm volatile(                                                             \
        "mma.sync.aligned.m16n8k16.row.col.f32.f16.f16.f32 "                  \
        "{%0,%1,%2,%3}, {%4,%5,%6,%7}, {%8,%9}, {%0,%1,%2,%3};"               \
        : "+f"(d0), "+f"(d1), "+f"(d2), "+f"(d3)                              \
        : "r"((A).x), "r"((A).y), "r"((A).z), "r"((A).w), "r"(b0), "r"(b1))

// SMEM: [0,32K) B frags; [32K,48K) A buf0; [48K,64K) A buf1.
static constexpr int SMEM_BF = 0;
static constexpr int SMEM_A0 = 32768;
static constexpr int SMEM_TOTAL = 65536;

// ---------------------------------------------------------------------------
// 8 warps: thread (wid=kt, lane) produces A quads for mt=0..3 of each tile.
// Stage 2: warp = (mgroup = wid>>2) x (ngroup = wid&3), 32r x 32c tile.
// ---------------------------------------------------------------------------
__global__ __launch_bounds__(256, 3) void fused_tanh_gemm_kernel(
    const float* __restrict__ x, const float* __restrict__ tanh_range,
    float* __restrict__ out)
{
    extern __shared__ __align__(16) char smem[];
    const int tid = threadIdx.x;
    const int lane = tid & 31;
    const int wid = tid >> 5;
    const int mgroup = wid >> 2;
    const int ngroup = wid & 3;

    // ---- B fragments -> SMEM, once per CTA ----
    {
        const uint4* src = reinterpret_cast<const uint4*>(g_BF);
        uint4* dst = reinterpret_cast<uint4*>(smem + SMEM_BF);
#pragma unroll
        for (int i = tid; i < 2048; i += 256) dst[i] = __ldg(&src[i]);
    }

    const float t = __ldg(tanh_range);
    const size_t row0 = (size_t)blockIdx.x * (TILE_M * TILES);
    // this thread's x sampling base: row (lane>>2), col wid*16 + (lane&3)*2
    const float* xb = x + row0 * IDIM + (size_t)(lane >> 2) * IDIM
                    + wid * 16 + ((lane & 3) << 1);

    // xr[i*4 + {0,1,2,3}] = x at (i*16 + r, c), (..+8, c), (.., c+8), (..+8, c+8)
    float2 xr[16];
#pragma unroll
    for (int i = 0; i < 4; i++) {
        const float* p = xb + (size_t)i * 16 * IDIM;
        xr[i * 4 + 0] = __ldcs(reinterpret_cast<const float2*>(p));
        xr[i * 4 + 1] = __ldcs(reinterpret_cast<const float2*>(p + 8 * IDIM));
        xr[i * 4 + 2] = __ldcs(reinterpret_cast<const float2*>(p + 8));
        xr[i * 4 + 3] = __ldcs(reinterpret_cast<const float2*>(p + 8 * IDIM + 8));
    }

    for (int tt = 0; tt < TILES; tt++) {
        char* abuf = smem + SMEM_A0 + ((tt & 1) << 14);

        // ---- stage 1: tanh + pack + STS fragments ----
#pragma unroll
        for (int i = 0; i < 4; i++) {
            uint4 quad;
            quad.x = pack_h2(tanh_acc(xr[i * 4 + 0].x * t), tanh_acc(xr[i * 4 + 0].y * t));
            quad.y = pack_h2(tanh_acc(xr[i * 4 + 1].x * t), tanh_acc(xr[i * 4 + 1].y * t));
            quad.z = pack_h2(tanh_acc(xr[i * 4 + 2].x * t), tanh_acc(xr[i * 4 + 2].y * t));
            quad.w = pack_h2(tanh_acc(xr[i * 4 + 3].x * t), tanh_acc(xr[i * 4 + 3].y * t));
            *reinterpret_cast<uint4*>(abuf + (((i * 8 + wid) * 32 + lane) << 4)) = quad;
        }
        __syncthreads();

        const bool more = (tt + 1 < TILES);
        const float* xn = xb + (size_t)(tt + 1) * TILE_M * IDIM;
        if (more) {   // prefetch half 1 (mt=0,1) of next tile
#pragma unroll
            for (int i = 0; i < 2; i++) {
                const float* p = xn + (size_t)i * 16 * IDIM;
                xr[i * 4 + 0] = __ldcs(reinterpret_cast<const float2*>(p));
                xr[i * 4 + 1] = __ldcs(reinterpret_cast<const float2*>(p + 8 * IDIM));
                xr[i * 4 + 2] = __ldcs(reinterpret_cast<const float2*>(p + 8));
                xr[i * 4 + 3] = __ldcs(reinterpret_cast<const float2*>(p + 8 * IDIM + 8));
            }
        }

        // ---- stage 2: MMA ----
        float acc[2][4][4];
#pragma unroll
        for (int a = 0; a < 2; a++)
#pragma unroll
            for (int b = 0; b < 4; b++)
#pragma unroll
                for (int cc = 0; cc < 4; cc++) acc[a][b][cc] = 0.f;

#pragma unroll
        for (int kt = 0; kt < 8; kt++) {
            if (kt == 4 && more) {   // prefetch half 2 (mt=2,3)
#pragma unroll
                for (int i = 2; i < 4; i++) {
                    const float* p = xn + (size_t)i * 16 * IDIM;
                    xr[i * 4 + 0] = __ldcs(reinterpret_cast<const float2*>(p));
                    xr[i * 4 + 1] = __ldcs(reinterpret_cast<const float2*>(p + 8 * IDIM));
                    xr[i * 4 + 2] = __ldcs(reinterpret_cast<const float2*>(p + 8));
                    xr[i * 4 + 3] = __ldcs(reinterpret_cast<const float2*>(p + 8 * IDIM + 8));
                }
            }
            uint4 af[2];
#pragma unroll
            for (int mt = 0; mt < 2; mt++) {
                int mtg = mgroup * 2 + mt;
                af[mt] = *reinterpret_cast<const uint4*>(
                    abuf + (((mtg * 8 + kt) * 32 + lane) << 4));
            }
#pragma unroll
            for (int nt = 0; nt < 4; nt++) {
                int ntg = ngroup * 4 + nt;
                uint2 bh = *reinterpret_cast<const uint2*>(
                    smem + SMEM_BF + (((ntg * 8 + kt) * 32 + lane) << 3));
#pragma unroll
                for (int mt = 0; mt < 2; mt++)
                    MMA16816(acc[mt][nt][0], acc[mt][nt][1], acc[mt][nt][2], acc[mt][nt][3],
                             af[mt], bh.x, bh.y);
            }
        }

        // ---- epilogue ----
        const size_t trow = row0 + (size_t)tt * TILE_M;
#pragma unroll
        for (int mt = 0; mt < 2; mt++) {
            int r0 = mgroup * 32 + mt * 16 + (lane >> 2);
#pragma unroll
            for (int nt = 0; nt < 4; nt++) {
                int c0 = ngroup * 32 + nt * 8 + ((lane & 3) << 1);
                float* o = out + (trow + r0) * ODIM + c0;
                __stcs(reinterpret_cast<float2*>(o),
                       make_float2(acc[mt][nt][0], acc[mt][nt][1]));
                __stcs(reinterpret_cast<float2*>(o + 8 * ODIM),
                       make_float2(acc[mt][nt][2], acc[mt][nt][3]));
            }
        }
    }
}

// ---------------------------------------------------------------------------
extern "C" void kernel_launch(void* const* d_in, const int* in_sizes, int n_in,
                              void* d_out, int out_size) {
    const float* x = (const float*)d_in[0];
    const float* coef = (const float*)d_in[1];
    const float* tr = (const float*)d_in[2];
    float* out = (float*)d_out;

    cudaFuncSetAttribute(fused_tanh_gemm_kernel,
                         cudaFuncAttributeMaxDynamicSharedMemorySize, SMEM_TOTAL);

    prep_w_kernel<<<32, 256>>>(coef);

    int rows = in_sizes[0] / IDIM;                 // 131072
    int grid = rows / (TILE_M * TILES);            // 512
    fused_tanh_gemm_kernel<<<grid, 256, SMEM_TOTAL>>>(x, tr, out);
}

// round 5
// speedup vs baseline: 1.7382x; 1.7382x over previous
#include <cuda_runtime.h>
#include <cuda_fp16.h>
#include <cstdint>

// out[b,o] = sum_i tanh(x[b,i]*t) * W[o,i],  W = sum_p coef[o,i,p]
// B=131072, I=O=128. fp32 in/out.
//
// mma.sync.m16n8k16 fp16 (fp32 accum), fp16 W (rel_err ~2.7e-4).
// R3 geometry (TILE_M=64, grid=2048, 8 warps) + coalesced stage-1 with
// XOR-swizzled A tile + ldmatrix.x4 + B fragments via __ldg (L1-resident).

static constexpr int IDIM = 128;
static constexpr int ODIM = 128;
static constexpr int TILE_M = 64;

// B fragments in mma register layout: [nt(16)][kt(8)][lane(32)][reg(2)]
__device__ uint32_t g_BF[16 * 8 * 32 * 2];   // 32KB, L1/L2-hot

// ---------------------------------------------------------------------------
__global__ void prep_w_kernel(const float* __restrict__ coef) {
    int idx = blockIdx.x * blockDim.x + threadIdx.x;   // 0..8191
    int nt = idx >> 9;
    int kt = (idx >> 6) & 7;
    int lane = (idx >> 1) & 31;
    int reg = idx & 1;
    int n = nt * 8 + (lane >> 2);
    int k = kt * 16 + (lane & 3) * 2 + reg * 8;

    const float4* c0 = reinterpret_cast<const float4*>(coef + ((size_t)n * 128 + k) * 16);
    const float4* c1 = reinterpret_cast<const float4*>(coef + ((size_t)n * 128 + k + 1) * 16);
    float4 v[8];
#pragma unroll
    for (int j = 0; j < 4; j++) v[j] = c0[j];
#pragma unroll
    for (int j = 0; j < 4; j++) v[4 + j] = c1[j];
    float s0 = 0.f, s1 = 0.f;
#pragma unroll
    for (int j = 0; j < 4; j++) s0 += (v[j].x + v[j].y) + (v[j].z + v[j].w);
#pragma unroll
    for (int j = 0; j < 4; j++) s1 += (v[4 + j].x + v[4 + j].y) + (v[4 + j].z + v[4 + j].w);
    __half2 hh = __floats2half2_rn(s0, s1);
    g_BF[((nt * 8 + kt) * 32 + lane) * 2 + reg] = *reinterpret_cast<uint32_t*>(&hh);
}

// ---------------------------------------------------------------------------
__device__ __forceinline__ float tanh_acc(float v) {
    v = fminf(fmaxf(v, -10.f), 10.f);
    float e = __expf(2.f * v);
    return __fdividef(e - 1.f, e + 1.f);
}

__device__ __forceinline__ uint32_t pack_h2(float a, float b) {
    __half2 h = __floats2half2_rn(a, b);
    return *reinterpret_cast<uint32_t*>(&h);
}

#define MMA16816(d0, d1, d2, d3, a0, a1, a2, a3, b0, b1)                      \
    asm volatile(                                                             \
        "mma.sync.aligned.m16n8k16.row.col.f32.f16.f16.f32 "                  \
        "{%0,%1,%2,%3}, {%4,%5,%6,%7}, {%8,%9}, {%0,%1,%2,%3};"               \
        : "+f"(d0), "+f"(d1), "+f"(d2), "+f"(d3)                              \
        : "r"(a0), "r"(a1), "r"(a2), "r"(a3), "r"(b0), "r"(b1))

#define LDMATRIX_X4(a0, a1, a2, a3, addr)                                     \
    asm volatile(                                                             \
        "ldmatrix.sync.aligned.m8n8.x4.shared.b16 {%0,%1,%2,%3}, [%4];"       \
        : "=r"(a0), "=r"(a1), "=r"(a2), "=r"(a3) : "r"(addr))

// SMEM: A tile only — 64 rows x 128 halfs (256B/row), XOR-16B-swizzled.
static constexpr int SMEM_TOTAL = 16384;

// ---------------------------------------------------------------------------
// 8 warps. Stage 1: warp w writes rows w*8..w*8+7, one full row per pass
// (coalesced float4 LDG, conflict-free STS.64 into swizzled tile).
// Stage 2: warp = (mgroup = wid>>2) x (ngroup = wid&3), 32r x 32c tile;
// A via ldmatrix.x4, B fragments via __ldg (L1-hit after warmup).
// ---------------------------------------------------------------------------
__global__ __launch_bounds__(256, 4) void fused_tanh_gemm_kernel(
    const float* __restrict__ x, const float* __restrict__ tanh_range,
    float* __restrict__ out)
{
    extern __shared__ __align__(16) char smem[];
    uint32_t sbase;
    asm("{ .reg .u64 t; cvta.to.shared.u64 t, %1; cvt.u32.u64 %0, t; }"
        : "=r"(sbase) : "l"(smem));

    const int tid = threadIdx.x;
    const int lane = tid & 31;
    const int wid = tid >> 5;
    const int mgroup = wid >> 2;
    const int ngroup = wid & 3;
    const size_t rowBase = (size_t)blockIdx.x * TILE_M;

    // ---- stage 1: coalesced load + tanh + swizzled STS.64 ----
    {
        const float t = __ldg(tanh_range);
        const float4* x4 = reinterpret_cast<const float4*>(x + rowBase * IDIM);
#pragma unroll
        for (int p = 0; p < 8; p++) {
            int row = wid * 8 + p;
            float4 v = __ldcs(&x4[row * 32 + lane]);
            uint2 hp;
            hp.x = pack_h2(tanh_acc(v.x * t), tanh_acc(v.y * t));
            hp.y = pack_h2(tanh_acc(v.z * t), tanh_acc(v.w * t));
            // unswizzled col-byte = lane*8; XOR bits [4:6] by row&7
            uint32_t byte = (uint32_t)row * 256 + ((lane * 8) ^ ((row & 7) << 4));
            *reinterpret_cast<uint2*>(smem + byte) = hp;
        }
    }
    __syncthreads();

    // ---- stage 2: MMA ----
    float acc[2][4][4];
#pragma unroll
    for (int a = 0; a < 2; a++)
#pragma unroll
        for (int b = 0; b < 4; b++)
#pragma unroll
            for (int cc = 0; cc < 4; cc++) acc[a][b][cc] = 0.f;

    // per-lane ldmatrix geometry (row-within-16-tile, col-chunk, swizzle)
    const int lrow = ((lane >> 3) & 1) * 8 + (lane & 7);
    const uint32_t chi = (uint32_t)((lane >> 4) << 4);
    const uint32_t sw = (uint32_t)((lane & 7) << 4);   // (r&7)<<4, r&7 == lane&7

#pragma unroll
    for (int kt = 0; kt < 8; kt++) {
        uint32_t a0[2], a1[2], a2[2], a3[2];
#pragma unroll
        for (int mt = 0; mt < 2; mt++) {
            int mtg = mgroup * 2 + mt;
            int r = mtg * 16 + lrow;
            uint32_t addr = sbase + (uint32_t)r * 256 + (((uint32_t)kt * 32 + chi) ^ sw);
            LDMATRIX_X4(a0[mt], a1[mt], a2[mt], a3[mt], addr);
        }
#pragma unroll
        for (int nt = 0; nt < 4; nt++) {
            int ntg = ngroup * 4 + nt;
            uint2 bh = __ldg(reinterpret_cast<const uint2*>(
                g_BF + (((ntg * 8 + kt) * 32 + lane) << 1)));
#pragma unroll
            for (int mt = 0; mt < 2; mt++)
                MMA16816(acc[mt][nt][0], acc[mt][nt][1], acc[mt][nt][2], acc[mt][nt][3],
                         a0[mt], a1[mt], a2[mt], a3[mt], bh.x, bh.y);
        }
    }

    // ---- epilogue (unchanged from R3) ----
#pragma unroll
    for (int mt = 0; mt < 2; mt++) {
        int r0 = mgroup * 32 + mt * 16 + (lane >> 2);
#pragma unroll
        for (int nt = 0; nt < 4; nt++) {
            int c0 = ngroup * 32 + nt * 8 + ((lane & 3) << 1);
            float* o = out + (rowBase + r0) * ODIM + c0;
            __stcs(reinterpret_cast<float2*>(o),
                   make_float2(acc[mt][nt][0], acc[mt][nt][1]));
            __stcs(reinterpret_cast<float2*>(o + 8 * ODIM),
                   make_float2(acc[mt][nt][2], acc[mt][nt][3]));
        }
    }
}

// ---------------------------------------------------------------------------
extern "C" void kernel_launch(void* const* d_in, const int* in_sizes, int n_in,
                              void* d_out, int out_size) {
    const float* x = (const float*)d_in[0];
    const float* coef = (const float*)d_in[1];
    const float* tr = (const float*)d_in[2];
    float* out = (float*)d_out;

    cudaFuncSetAttribute(fused_tanh_gemm_kernel,
                         cudaFuncAttributeMaxDynamicSharedMemorySize, SMEM_TOTAL);

    prep_w_kernel<<<32, 256>>>(coef);

    int rows = in_sizes[0] / IDIM;     // 131072
    int grid = rows / TILE_M;          // 2048
    fused_tanh_gemm_kernel<<<grid, 256, SMEM_TOTAL>>>(x, tr, out);
}